// round 3
// baseline (speedup 1.0000x reference)
#include <cuda_runtime.h>
#include <cstdint>

#define NMAX 50000
#define EMAX 800000
#define CMAX 5000
#define DIN  128
#define DOUT 40

// Scratch (static device globals). g_cnt is self-restoring: zero at process
// start, accumulated by k_deg, reset to zero by k_scan on every replay.
__device__ int   g_cnt[NMAX];
__device__ int   g_rowptr[NMAX];      // CSR start offsets (in-edges per dst)
__device__ int   g_wpos[NMAX];        // fill cursor; after k_fill == end offsets
__device__ float g_dinv[NMAX];
__device__ int   g_csr_src[EMAX];
__device__ float g_csr_nrm[EMAX];     // dinv[src]*dinv[dst] per CSR entry
__device__ float g_y0[NMAX * DOUT];   // x @ W^T
__device__ float g_h1[NMAX * DOUT];   // after hop 1
__device__ float g_lsm[CMAX * DOUT];  // per-cluster log-softmax rows

__device__ __forceinline__ void fma2(unsigned long long& acc,
                                     unsigned long long a, unsigned long long b) {
    asm("fma.rn.f32x2 %0, %1, %2, %3;" : "=l"(acc) : "l"(a), "l"(b), "l"(acc));
}
__device__ __forceinline__ unsigned long long pack2(float v) {
    unsigned long long r;
    asm("mov.b64 %0, {%1, %1};" : "=l"(r) : "f"(v));
    return r;
}

// ---- 1) in-degree counts over dst ----
__global__ void k_deg(const int* __restrict__ dst, int e) {
    int i = blockIdx.x * blockDim.x + threadIdx.x;
    if (i >= e) return;
    atomicAdd(&g_cnt[dst[i]], 1);
}

// ---- 2) single-block exclusive scan -> rowptr/wpos, dinv; resets g_cnt ----
__global__ void k_scan(int n) {
    const int T = 1024;
    __shared__ int ssum[T];
    int tid = threadIdx.x;
    int chunk = (n + T - 1) / T;
    int lo = tid * chunk;
    int hi = lo + chunk; if (hi > n) hi = n;
    int s = 0;
    for (int v = lo; v < hi; v++) s += g_cnt[v];
    ssum[tid] = s;
    __syncthreads();
    // Hillis-Steele inclusive scan over 1024 partials
    for (int off = 1; off < T; off <<= 1) {
        int val = (tid >= off) ? ssum[tid - off] : 0;
        __syncthreads();
        ssum[tid] += val;
        __syncthreads();
    }
    int run = (tid > 0) ? ssum[tid - 1] : 0;
    for (int v = lo; v < hi; v++) {
        int c = g_cnt[v];
        g_rowptr[v] = run;
        g_wpos[v]   = run;
        g_dinv[v]   = rsqrtf((float)(c + 1));   // +1 = self loop
        g_cnt[v]    = 0;                        // self-restore for next replay
        run += c;
    }
}

// ---- 3) CSR fill: (src, norm) per in-edge of dst ----
__global__ void k_fill(const int* __restrict__ src, const int* __restrict__ dst, int e) {
    int i = blockIdx.x * blockDim.x + threadIdx.x;
    if (i >= e) return;
    int s = src[i], d = dst[i];
    int p = atomicAdd(&g_wpos[d], 1);
    g_csr_src[p] = s;
    g_csr_nrm[p] = g_dinv[s] * g_dinv[d];
}

// ---- 4) projection y0 = x @ W^T with packed f32x2 FMA ----
__global__ void k_project(const float* __restrict__ x, const float* __restrict__ W, int n) {
    // Wp[k*40+o] = W[o][k]   (transposed so per-k rows are contiguous, 160B, 16B aligned)
    __shared__ float Wp[DIN * DOUT];  // 20 KB
    for (int i = threadIdx.x; i < DIN * DOUT; i += blockDim.x) {
        int k = i / DOUT, o = i % DOUT;
        Wp[i] = W[o * DIN + k];
    }
    __syncthreads();
    int v = blockIdx.x * blockDim.x + threadIdx.x;
    if (v >= n) return;

    unsigned long long acc[DOUT / 2];
#pragma unroll
    for (int j = 0; j < DOUT / 2; j++) acc[j] = 0ull;

    const float4* xr = (const float4*)(x + (size_t)v * DIN);
#pragma unroll 4
    for (int k4 = 0; k4 < DIN / 4; k4++) {
        float4 xv = xr[k4];
        float xs[4] = {xv.x, xv.y, xv.z, xv.w};
#pragma unroll
        for (int kk = 0; kk < 4; kk++) {
            int k = k4 * 4 + kk;
            unsigned long long xp = pack2(xs[kk]);
            const ulonglong2* wrow = (const ulonglong2*)(Wp + k * DOUT);
#pragma unroll
            for (int g = 0; g < DOUT / 4; g++) {
                ulonglong2 w = wrow[g];      // LDS.128, broadcast (all lanes same addr)
                fma2(acc[2 * g],     xp, w.x);
                fma2(acc[2 * g + 1], xp, w.y);
            }
        }
    }
    float4* y = (float4*)(g_y0 + (size_t)v * DOUT);
#pragma unroll
    for (int g = 0; g < DOUT / 4; g++) {
        float2 a = *(float2*)&acc[2 * g];
        float2 b = *(float2*)&acc[2 * g + 1];
        y[g] = make_float4(a.x, a.y, b.x, b.y);
    }
}

// ---- 5) hop1 gather: warp per node, lane j owns feature j (+ j+32 for j<8) ----
__global__ void k_hop1(int n) {
    int gw  = (blockIdx.x * blockDim.x + threadIdx.x) >> 5;
    int lid = threadIdx.x & 31;
    if (gw >= n) return;
    int node = gw;
    float di = g_dinv[node];
    float d2 = di * di;
    const float* selfrow = g_y0 + (size_t)node * DOUT;
    float acc0 = d2 * selfrow[lid];
    float acc1 = (lid < 8) ? d2 * selfrow[32 + lid] : 0.0f;

    int start = g_rowptr[node];
    int end   = g_wpos[node];
    for (int base = start; base < end; base += 32) {
        int m = end - base; if (m > 32) m = 32;
        int s = 0; float nm = 0.0f;
        if (lid < m) { s = g_csr_src[base + lid]; nm = g_csr_nrm[base + lid]; }
        for (int k = 0; k < m; k++) {
            int   ss = __shfl_sync(0xffffffffu, s,  k);
            float nn = __shfl_sync(0xffffffffu, nm, k);
            const float* row = g_y0 + (size_t)ss * DOUT;
            acc0 += nn * row[lid];                     // coalesced 128B
            if (lid < 8) acc1 += nn * row[32 + lid];   // coalesced 32B
        }
    }
    float* h = g_h1 + (size_t)node * DOUT;
    h[lid] = acc0;
    if (lid < 8) h[32 + lid] = acc1;
}

// ---- 6) hop2 gather + bias + log_softmax, warp per cluster ----
__global__ void k_hop2lsm(const int* __restrict__ rep_idx, const float* __restrict__ b, int c) {
    int gw  = (blockIdx.x * blockDim.x + threadIdx.x) >> 5;
    int lid = threadIdx.x & 31;
    if (gw >= c) return;
    int r = rep_idx[gw];
    float di = g_dinv[r];
    float d2 = di * di;
    const float* selfrow = g_h1 + (size_t)r * DOUT;
    float acc0 = d2 * selfrow[lid];
    float acc1 = (lid < 8) ? d2 * selfrow[32 + lid] : 0.0f;

    int start = g_rowptr[r];
    int end   = g_wpos[r];
    for (int base = start; base < end; base += 32) {
        int m = end - base; if (m > 32) m = 32;
        int s = 0; float nm = 0.0f;
        if (lid < m) { s = g_csr_src[base + lid]; nm = g_csr_nrm[base + lid]; }
        for (int k = 0; k < m; k++) {
            int   ss = __shfl_sync(0xffffffffu, s,  k);
            float nn = __shfl_sync(0xffffffffu, nm, k);
            const float* row = g_h1 + (size_t)ss * DOUT;
            acc0 += nn * row[lid];
            if (lid < 8) acc1 += nn * row[32 + lid];
        }
    }
    acc0 += b[lid];
    float a1 = -3.4e38f;
    if (lid < 8) { acc1 += b[32 + lid]; a1 = acc1; }
    // max over 40 values
    float mx = fmaxf(acc0, a1);
#pragma unroll
    for (int o = 16; o > 0; o >>= 1) mx = fmaxf(mx, __shfl_xor_sync(0xffffffffu, mx, o));
    float es = expf(acc0 - mx) + ((lid < 8) ? expf(acc1 - mx) : 0.0f);
#pragma unroll
    for (int o = 16; o > 0; o >>= 1) es += __shfl_xor_sync(0xffffffffu, es, o);
    float l = logf(es) + mx;
    float* outp = g_lsm + (size_t)gw * DOUT;
    outp[lid] = acc0 - l;
    if (lid < 8) outp[32 + lid] = acc1 - l;
}

// ---- 7) broadcast per-cluster rows to all nodes ----
__global__ void k_bcast(const int* __restrict__ cluster_index, float* __restrict__ out, int n) {
    int idx = blockIdx.x * blockDim.x + threadIdx.x;
    int total = n * (DOUT / 4);
    if (idx >= total) return;
    int i = idx / (DOUT / 4);
    int j = idx % (DOUT / 4);
    int c = cluster_index[i];
    ((float4*)out)[idx] = ((const float4*)g_lsm)[c * (DOUT / 4) + j];
}

extern "C" void kernel_launch(void* const* d_in, const int* in_sizes, int n_in,
                              void* d_out, int out_size) {
    const float* x       = (const float*)d_in[0];
    const int*   edge    = (const int*)d_in[1];
    const int*   cluster = (const int*)d_in[2];
    const int*   rep     = (const int*)d_in[3];
    const float* W       = (const float*)d_in[4];
    const float* b       = (const float*)d_in[5];
    float* out = (float*)d_out;

    int n = in_sizes[0] / DIN;
    int e = in_sizes[1] / 2;
    int c = in_sizes[3];
    const int* src = edge;
    const int* dst = edge + e;

    const int B = 256;
    k_deg    <<<(e + B - 1) / B, B>>>(dst, e);
    k_scan   <<<1, 1024>>>(n);
    k_fill   <<<(e + B - 1) / B, B>>>(src, dst, e);
    k_project<<<(n + B - 1) / B, B>>>(x, W, n);
    k_hop1   <<<(n * 32 + B - 1) / B, B>>>(n);
    k_hop2lsm<<<(c * 32 + B - 1) / B, B>>>(rep, b, c);
    int tot = n * (DOUT / 4);
    k_bcast  <<<(tot + B - 1) / B, B>>>(cluster, out, n);
}